// round 7
// baseline (speedup 1.0000x reference)
#include <cuda_runtime.h>

// GraphAggregation: out[b][d] = mean over 196 nodes of in[b][n*4 + d]
// in:  (B, 784) float32   out: (B, 4) float32
//
// HBM-streaming bound (~416 MB traffic, measured 6.79 TB/s at 2 rows/warp).
// Each warp owns 4 ADJACENT rows (page/TLB locality). 24 full-warp float4
// loads + one merged 16-lane tail are front-batched for max MLP.
// launch_bounds(256,2) -> up to 128 regs so the batch isn't serialized.

__global__ void __launch_bounds__(256, 2)
graph_agg_kernel(const float4* __restrict__ in, float4* __restrict__ out, int B4)
{
    const int lane = threadIdx.x & 31;
    const int warp = (int)((blockIdx.x * (unsigned)blockDim.x + threadIdx.x) >> 5);
    if (warp >= B4) return;              // B4 = B/4 row-quads

    const int r = warp * 4;
    const float4* base = in + (size_t)r * 196;   // 4*196 = 784 contiguous float4s

    // ---- front-batched independent loads: 24 full + 1 merged tail ----
    // Full-warp loads cover float4 indices [0, 768) of the 784-float4 group.
    float4 v[24];
    #pragma unroll
    for (int k = 0; k < 24; ++k) v[k] = __ldg(base + k * 32 + lane);

    // Tail: indices 768..783 (16 float4s). Lane l < 16 loads base[768+l].
    // Row ownership: rows are 196 float4s -> tail lanes 0-3 belong to row A
    // (indices 192..195 of row 0 => 768+0..3? no: row0 covers [0,196)).
    // Careful: the 24 full loads interleave rows; ownership must be computed
    // per absolute index. Absolute index of v[k] lane l is k*32+l; its row is
    // (k*32+l)/196, its purpose is just a component-wise sum per row. We
    // therefore accumulate per-row by masking on the row id of each element.
    float4 t = make_float4(0.f, 0.f, 0.f, 0.f);
    if (lane < 16) t = __ldg(base + 768 + lane);

    // ---- per-row accumulation ----
    // acc[j] accumulates this thread's elements belonging to row j.
    float ax[4] = {0.f,0.f,0.f,0.f};
    float ay[4] = {0.f,0.f,0.f,0.f};
    float az[4] = {0.f,0.f,0.f,0.f};
    float aw[4] = {0.f,0.f,0.f,0.f};

    #pragma unroll
    for (int k = 0; k < 24; ++k) {
        const int idx = k * 32 + lane;       // 0..767
        const int row = idx / 196;           // 0..3 (lane-dependent only via idx)
        ax[0] += (row == 0) ? v[k].x : 0.f;  // compiler turns these into SELs/predicated adds
        ay[0] += (row == 0) ? v[k].y : 0.f;
        az[0] += (row == 0) ? v[k].z : 0.f;
        aw[0] += (row == 0) ? v[k].w : 0.f;
        ax[1] += (row == 1) ? v[k].x : 0.f;
        ay[1] += (row == 1) ? v[k].y : 0.f;
        az[1] += (row == 1) ? v[k].z : 0.f;
        aw[1] += (row == 1) ? v[k].w : 0.f;
        ax[2] += (row == 2) ? v[k].x : 0.f;
        ay[2] += (row == 2) ? v[k].y : 0.f;
        az[2] += (row == 2) ? v[k].z : 0.f;
        aw[2] += (row == 2) ? v[k].w : 0.f;
        ax[3] += (row == 3) ? v[k].x : 0.f;
        ay[3] += (row == 3) ? v[k].y : 0.f;
        az[3] += (row == 3) ? v[k].z : 0.f;
        aw[3] += (row == 3) ? v[k].w : 0.f;
    }
    // Tail element: absolute index 768+lane (lane<16), row = (768+lane)/196 = 3
    // for lane in [0,16) since 768/196 = 3 (768..783 all in row 3: row3 spans
    // 588..783). All tail elements belong to row 3.
    az[3] += t.z; aw[3] += t.w; ax[3] += t.x; ay[3] += t.y;

    // ---- butterfly reductions (4 rows x 4 components) ----
    #pragma unroll
    for (int off = 16; off > 0; off >>= 1) {
        #pragma unroll
        for (int j = 0; j < 4; ++j) {
            ax[j] += __shfl_xor_sync(0xffffffffu, ax[j], off);
            ay[j] += __shfl_xor_sync(0xffffffffu, ay[j], off);
            az[j] += __shfl_xor_sync(0xffffffffu, az[j], off);
            aw[j] += __shfl_xor_sync(0xffffffffu, aw[j], off);
        }
    }

    if (lane == 0) {
        const float s = 1.0f / 196.0f;
        #pragma unroll
        for (int j = 0; j < 4; ++j)
            out[r + j] = make_float4(ax[j] * s, ay[j] * s, az[j] * s, aw[j] * s);
    }
}

extern "C" void kernel_launch(void* const* d_in, const int* in_sizes, int n_in,
                              void* d_out, int out_size)
{
    const float4* in  = (const float4*)d_in[0];
    float4*       out = (float4*)d_out;
    const int B  = in_sizes[0] / 784;         // 131072 (divisible by 4)
    const int B4 = B / 4;                     // row-quads: 32768

    const int threads = 256;                  // 8 warps/block -> 32 rows/block
    const int blocks  = (B4 + 7) / 8;         // 4096

    graph_agg_kernel<<<blocks, threads>>>(in, out, B4);
}

// round 10
// speedup vs baseline: 1.0258x; 1.0258x over previous
#include <cuda_runtime.h>

// GraphAggregation: out[b][d] = mean over 196 nodes of in[b][n*4 + d]
// in:  (B, 784) float32   out: (B, 4) float32
//
// FINAL: HBM-streaming bound. Measured streaming roofline on this part is
// ~6.79 TB/s (85% of 8 TB/s spec); both 2-row and 4-row MLP variants saturate
// it. This is the 2-rows-per-warp variant (best bench time, regs=62):
//  - each warp owns 2 ADJACENT rows (page/TLB locality — grid-stride hurt by
//    ~230 MB of extra page-walk traffic in R2)
//  - 13 independent float4 loads front-batched (12 full-warp + merged tail)
//  - launch_bounds(256,3) so ptxas keeps the whole batch in flight (62 regs)

__global__ void __launch_bounds__(256, 3)
graph_agg_kernel(const float4* __restrict__ in, float4* __restrict__ out, int B2)
{
    const int lane = threadIdx.x & 31;
    const int warp = (int)((blockIdx.x * (unsigned)blockDim.x + threadIdx.x) >> 5);
    if (warp >= B2) return;              // B2 = B/2 row-pairs

    const int r = warp * 2;
    const float4* rowA = in + (size_t)r * 196;
    const float4* rowB = rowA + 196;

    // ---- front-batched independent loads ----
    float4 va[6], vb[6];
    #pragma unroll
    for (int k = 0; k < 6; ++k) va[k] = __ldg(rowA + k * 32 + lane);
    #pragma unroll
    for (int k = 0; k < 6; ++k) vb[k] = __ldg(rowB + k * 32 + lane);

    // merged tail: lanes 0-3 load rowA[192..195], lanes 4-7 load rowB[192..195]
    float4 t = make_float4(0.f, 0.f, 0.f, 0.f);
    if (lane < 8) {
        const float4* tp = (lane < 4) ? (rowA + 192 + lane) : (rowB + 188 + lane);
        t = __ldg(tp);
    }

    // ---- accumulate ----
    float ax = 0.f, ay = 0.f, az = 0.f, aw = 0.f;
    float bx = 0.f, by = 0.f, bz = 0.f, bw = 0.f;
    #pragma unroll
    for (int k = 0; k < 6; ++k) {
        ax += va[k].x; ay += va[k].y; az += va[k].z; aw += va[k].w;
        bx += vb[k].x; by += vb[k].y; bz += vb[k].z; bw += vb[k].w;
    }
    if (lane < 4)              { ax += t.x; ay += t.y; az += t.z; aw += t.w; }
    else                       { bx += t.x; by += t.y; bz += t.z; bw += t.w; }

    // ---- butterfly reductions ----
    #pragma unroll
    for (int off = 16; off > 0; off >>= 1) {
        ax += __shfl_xor_sync(0xffffffffu, ax, off);
        ay += __shfl_xor_sync(0xffffffffu, ay, off);
        az += __shfl_xor_sync(0xffffffffu, az, off);
        aw += __shfl_xor_sync(0xffffffffu, aw, off);
        bx += __shfl_xor_sync(0xffffffffu, bx, off);
        by += __shfl_xor_sync(0xffffffffu, by, off);
        bz += __shfl_xor_sync(0xffffffffu, bz, off);
        bw += __shfl_xor_sync(0xffffffffu, bw, off);
    }

    if (lane == 0) {
        const float s = 1.0f / 196.0f;
        out[r]     = make_float4(ax * s, ay * s, az * s, aw * s);
        out[r + 1] = make_float4(bx * s, by * s, bz * s, bw * s);
    }
}

extern "C" void kernel_launch(void* const* d_in, const int* in_sizes, int n_in,
                              void* d_out, int out_size)
{
    const float4* in  = (const float4*)d_in[0];
    float4*       out = (float4*)d_out;
    const int B  = in_sizes[0] / 784;         // 131072 (even)
    const int B2 = B / 2;                     // row-pairs

    const int threads = 256;                  // 8 warps/block -> 16 rows/block
    const int blocks  = (B2 + 7) / 8;         // 8192

    graph_agg_kernel<<<blocks, threads>>>(in, out, B2);
}